// round 13
// baseline (speedup 1.0000x reference)
#include <cuda_runtime.h>
#include <cuda_fp16.h>
#include <math.h>
#include <stdint.h>

#define T  8192
#define H  512
#define E  8
#define IM 1024
#define IS 2048

#define BKH  64   // K-chunk in halves (128 B per row)
#define ASTR 36   // words per row: 32 data + 4 pad = 144 B

// ---------------- device scratch (allocation-free) ----------------
__device__ int    g_cnt[E];
__device__ int    g_tok[E * T];
__device__ float  g_wt[E * T];
__device__ float  g_sgate[T];
__device__ __align__(16) __half g_h[(size_t)E * T * IM];
__device__ __align__(16) __half g_hs[(size_t)T * IS];
__device__ __align__(16) __half g_xh[(size_t)T * H];
__device__ __align__(16) __half g_w1h[(size_t)E * IM * H];
__device__ __align__(16) __half g_w3h[(size_t)E * IM * H];
__device__ __align__(16) __half g_w2h[(size_t)E * H * IM];
__device__ __align__(16) __half g_sw1h[(size_t)IS * H];
__device__ __align__(16) __half g_sw3h[(size_t)IS * H];
__device__ __align__(16) __half g_sw2h[(size_t)H * IS];

// ---------------- helpers ----------------
__device__ __forceinline__ void mma16(float* c,
        uint32_t a0, uint32_t a1, uint32_t a2, uint32_t a3,
        uint32_t b0, uint32_t b1) {
    asm volatile(
        "mma.sync.aligned.m16n8k16.row.col.f32.f16.f16.f32 "
        "{%0,%1,%2,%3}, {%4,%5,%6,%7}, {%8,%9}, {%0,%1,%2,%3};"
        : "+f"(c[0]), "+f"(c[1]), "+f"(c[2]), "+f"(c[3])
        : "r"(a0), "r"(a1), "r"(a2), "r"(a3), "r"(b0), "r"(b1));
}
__device__ __forceinline__ float silu_f(float v) { return v / (1.f + __expf(-v)); }
__device__ __forceinline__ uint32_t sptr(const void* p) {
    return (uint32_t)__cvta_generic_to_shared(p);
}
__device__ __forceinline__ void cp16(uint32_t dst, const void* src, int sz) {
    asm volatile("cp.async.cg.shared.global [%0], [%1], 16, %2;"
                 :: "r"(dst), "l"(src), "r"(sz));
}
#define CP_COMMIT() asm volatile("cp.async.commit_group;")
#define CP_WAIT1()  asm volatile("cp.async.wait_group 1;")

// ---------------- prologue: fp32 -> fp16 ----------------
__global__ void k_to_half(const float* __restrict__ src, __half* __restrict__ dst, int n8) {
    int i = blockIdx.x * blockDim.x + threadIdx.x;
    if (i >= n8) return;
    const float4* s4 = (const float4*)src;
    float4 v0 = s4[2 * i], v1 = s4[2 * i + 1];
    __half2 h0 = __floats2half2_rn(v0.x, v0.y);
    __half2 h1 = __floats2half2_rn(v0.z, v0.w);
    __half2 h2 = __floats2half2_rn(v1.x, v1.y);
    __half2 h3 = __floats2half2_rn(v1.z, v1.w);
    uint4 o;
    o.x = *(uint32_t*)&h0; o.y = *(uint32_t*)&h1;
    o.z = *(uint32_t*)&h2; o.w = *(uint32_t*)&h3;
    ((uint4*)dst)[i] = o;
}

__global__ void k_zero_cnt() {
    if (threadIdx.x < E) g_cnt[threadIdx.x] = 0;
}

// One warp per token: router logits (fp32), softmax, top-2 dispatch, sigmoid gate.
__global__ void k_router(const float* __restrict__ x, const float* __restrict__ gw,
                         const float* __restrict__ sgw, float* __restrict__ logits_out) {
    const int warp = threadIdx.x >> 5;
    const int lane = threadIdx.x & 31;
    const int t = blockIdx.x * 8 + warp;
    if (t >= T) return;

    float xv[16];
    const float* xr = x + (size_t)t * H;
#pragma unroll
    for (int i = 0; i < 16; i++) xv[i] = xr[lane + 32 * i];

    float l[E];
#pragma unroll
    for (int e = 0; e < E; e++) {
        const float* w = gw + (size_t)e * H;
        float s = 0.f;
#pragma unroll
        for (int i = 0; i < 16; i++) s = fmaf(xv[i], w[lane + 32 * i], s);
#pragma unroll
        for (int off = 16; off > 0; off >>= 1) s += __shfl_xor_sync(0xffffffffu, s, off);
        l[e] = s;
    }
    float sd = 0.f;
#pragma unroll
    for (int i = 0; i < 16; i++) sd = fmaf(xv[i], sgw[lane + 32 * i], sd);
#pragma unroll
    for (int off = 16; off > 0; off >>= 1) sd += __shfl_xor_sync(0xffffffffu, sd, off);

    if (lane == 0) {
        if (logits_out) {
#pragma unroll
            for (int e = 0; e < E; e++) logits_out[(size_t)t * E + e] = l[e];
        }
        float m = l[0];
#pragma unroll
        for (int e = 1; e < E; e++) m = fmaxf(m, l[e]);
        float p[E], s = 0.f;
#pragma unroll
        for (int e = 0; e < E; e++) { p[e] = expf(l[e] - m); s += p[e]; }
        float inv = 1.f / s;
#pragma unroll
        for (int e = 0; e < E; e++) p[e] *= inv;
        int i1 = 0;
#pragma unroll
        for (int e = 1; e < E; e++) if (p[e] > p[i1]) i1 = e;
        int i2 = (i1 == 0) ? 1 : 0;
#pragma unroll
        for (int e = 0; e < E; e++) if (e != i1 && p[e] > p[i2]) i2 = e;

        int pos1 = atomicAdd(&g_cnt[i1], 1);
        g_tok[i1 * T + pos1] = t; g_wt[i1 * T + pos1] = p[i1];
        int pos2 = atomicAdd(&g_cnt[i2], 1);
        g_tok[i2 * T + pos2] = t; g_wt[i2 * T + pos2] = p[i2];

        g_sgate[t] = 1.f / (1.f + expf(-sd));
    }
}

// =====================================================================
// FP16 tensor-core GEMMs (m16n8k16, fp32 accumulate).
// K-chunk = 64 halves, 2-stage cp.async pipeline, 73.7 KB smem (2 CTA/SM).
// 256 threads = 8 warps, 4(m) x 2(n).
// =====================================================================

// Routed up-projection (dual GEMM): BM=128, BN=64, warp tile 32x32.
__global__ __launch_bounds__(256) void k_up_routed_tc(
        const __half* __restrict__ xq,
        const __half* __restrict__ w1,
        const __half* __restrict__ w3) {
    const int e = blockIdx.z;
    const int ne = g_cnt[e];
    const int row0 = blockIdx.y * 128;
    if (row0 >= ne) return;
    const int col0 = blockIdx.x * 64;
    const int* toks = g_tok + e * T;

    extern __shared__ uint32_t smem[];
    uint32_t* As  = smem;                       // 2 * 128*ASTR
    uint32_t* B1s = smem + 2 * 128 * ASTR;      // 2 * 64*ASTR
    uint32_t* B3s = B1s + 2 * 64 * ASTR;        // 2 * 64*ASTR

    const int tid = threadIdx.x;
    const int lane = tid & 31, wid = tid >> 5;
    const int qid = lane >> 2, tig = lane & 3;
    const int wm = wid & 3, wn = wid >> 2;
    const int lr = tid >> 3;
    const int lch = (tid & 7) * 8;
    const int lcw = (tid & 7) * 4;

    int atok[4];
#pragma unroll
    for (int q = 0; q < 4; q++) {
        int r = row0 + lr + q * 32;
        atok[q] = (r < ne) ? toks[r] : -1;
    }
    const __half* w1b = w1 + (size_t)e * IM * H + (size_t)col0 * H;
    const __half* w3b = w3 + (size_t)e * IM * H + (size_t)col0 * H;

    float acc1[2][4][4], acc3[2][4][4];
#pragma unroll
    for (int mi = 0; mi < 2; mi++)
#pragma unroll
        for (int ni = 0; ni < 4; ni++)
#pragma unroll
            for (int r = 0; r < 4; r++) { acc1[mi][ni][r] = 0.f; acc3[mi][ni][r] = 0.f; }

    auto load_tile = [&](int buf, int k0) {
        uint32_t* Ab  = As  + buf * 128 * ASTR;
        uint32_t* B1b = B1s + buf * 64 * ASTR;
        uint32_t* B3b = B3s + buf * 64 * ASTR;
#pragma unroll
        for (int q = 0; q < 4; q++) {
            int r = lr + q * 32;
            const __half* src = (atok[q] >= 0) ? (xq + (size_t)atok[q] * H + k0 + lch) : xq;
            cp16(sptr(&Ab[r * ASTR + lcw]), src, (atok[q] >= 0) ? 16 : 0);
        }
#pragma unroll
        for (int q = 0; q < 2; q++) {
            int r = lr + q * 32;
            cp16(sptr(&B1b[r * ASTR + lcw]), w1b + (size_t)r * H + k0 + lch, 16);
            cp16(sptr(&B3b[r * ASTR + lcw]), w3b + (size_t)r * H + k0 + lch, 16);
        }
    };

    const int NK = H / BKH;   // 8
    load_tile(0, 0);
    CP_COMMIT();
    for (int kt = 0; kt < NK; kt++) {
        int buf = kt & 1;
        if (kt + 1 < NK) load_tile(buf ^ 1, (kt + 1) * BKH);
        CP_COMMIT();
        CP_WAIT1();
        __syncthreads();
        uint32_t* Ab  = As  + buf * 128 * ASTR;
        uint32_t* B1b = B1s + buf * 64 * ASTR;
        uint32_t* B3b = B3s + buf * 64 * ASTR;
#pragma unroll
        for (int ks = 0; ks < 4; ks++) {
            const int kk = ks * 8 + tig;
            uint32_t a[2][4];
#pragma unroll
            for (int mi = 0; mi < 2; mi++) {
                int mb = wm * 32 + mi * 16;
                a[mi][0] = Ab[(mb + qid) * ASTR + kk];
                a[mi][1] = Ab[(mb + qid + 8) * ASTR + kk];
                a[mi][2] = Ab[(mb + qid) * ASTR + kk + 4];
                a[mi][3] = Ab[(mb + qid + 8) * ASTR + kk + 4];
            }
#pragma unroll
            for (int ni = 0; ni < 4; ni++) {
                int nb = (wn * 32 + ni * 8 + qid) * ASTR;
                uint32_t b10 = B1b[nb + kk], b11 = B1b[nb + kk + 4];
                uint32_t b30 = B3b[nb + kk], b31 = B3b[nb + kk + 4];
#pragma unroll
                for (int mi = 0; mi < 2; mi++) {
                    mma16(acc1[mi][ni], a[mi][0], a[mi][1], a[mi][2], a[mi][3], b10, b11);
                    mma16(acc3[mi][ni], a[mi][0], a[mi][1], a[mi][2], a[mi][3], b30, b31);
                }
            }
        }
        __syncthreads();
    }
#pragma unroll
    for (int mi = 0; mi < 2; mi++) {
        int rbase = row0 + wm * 32 + mi * 16 + qid;
#pragma unroll
        for (int half = 0; half < 2; half++) {
            int r = rbase + half * 8;
            if (r >= ne) continue;
            __half* orow = g_h + ((size_t)e * T + r) * IM + col0 + wn * 32;
#pragma unroll
            for (int ni = 0; ni < 4; ni++) {
                float v1a = acc1[mi][ni][half * 2], v1b = acc1[mi][ni][half * 2 + 1];
                float v3a = acc3[mi][ni][half * 2], v3b = acc3[mi][ni][half * 2 + 1];
                int c = ni * 8 + 2 * tig;
                orow[c]     = __float2half_rn(silu_f(v1a) * v3a);
                orow[c + 1] = __float2half_rn(silu_f(v1b) * v3b);
            }
        }
    }
}

// Shared up-projection (dual GEMM): BM=128, BN=64, warp tile 32x32.
__global__ __launch_bounds__(256) void k_up_shared_tc(
        const __half* __restrict__ xq,
        const __half* __restrict__ w1,
        const __half* __restrict__ w3) {
    const int row0 = blockIdx.y * 128;
    const int col0 = blockIdx.x * 64;

    extern __shared__ uint32_t smem[];
    uint32_t* As  = smem;
    uint32_t* B1s = smem + 2 * 128 * ASTR;
    uint32_t* B3s = B1s + 2 * 64 * ASTR;

    const int tid = threadIdx.x;
    const int lane = tid & 31, wid = tid >> 5;
    const int qid = lane >> 2, tig = lane & 3;
    const int wm = wid & 3, wn = wid >> 2;
    const int lr = tid >> 3;
    const int lch = (tid & 7) * 8;
    const int lcw = (tid & 7) * 4;

    const __half* w1b = w1 + (size_t)col0 * H;
    const __half* w3b = w3 + (size_t)col0 * H;

    float acc1[2][4][4], acc3[2][4][4];
#pragma unroll
    for (int mi = 0; mi < 2; mi++)
#pragma unroll
        for (int ni = 0; ni < 4; ni++)
#pragma unroll
            for (int r = 0; r < 4; r++) { acc1[mi][ni][r] = 0.f; acc3[mi][ni][r] = 0.f; }

    auto load_tile = [&](int buf, int k0) {
        uint32_t* Ab  = As  + buf * 128 * ASTR;
        uint32_t* B1b = B1s + buf * 64 * ASTR;
        uint32_t* B3b = B3s + buf * 64 * ASTR;
#pragma unroll
        for (int q = 0; q < 4; q++) {
            int r = lr + q * 32;
            cp16(sptr(&Ab[r * ASTR + lcw]), xq + (size_t)(row0 + r) * H + k0 + lch, 16);
        }
#pragma unroll
        for (int q = 0; q < 2; q++) {
            int r = lr + q * 32;
            cp16(sptr(&B1b[r * ASTR + lcw]), w1b + (size_t)r * H + k0 + lch, 16);
            cp16(sptr(&B3b[r * ASTR + lcw]), w3b + (size_t)r * H + k0 + lch, 16);
        }
    };

    const int NK = H / BKH;   // 8
    load_tile(0, 0);
    CP_COMMIT();
    for (int kt = 0; kt < NK; kt++) {
        int buf = kt & 1;
        if (kt + 1 < NK) load_tile(buf ^ 1, (kt + 1) * BKH);
        CP_COMMIT();
        CP_WAIT1();
        __syncthreads();
        uint32_t* Ab  = As  + buf * 128 * ASTR;
        uint32_t* B1b = B1s + buf * 64 * ASTR;
        uint32_t* B3b = B3s + buf * 64 * ASTR;
#pragma unroll
        for (int ks = 0; ks < 4; ks++) {
            const int kk = ks * 8 + tig;
            uint32_t a[2][4];
#pragma unroll
            for (int mi = 0; mi < 2; mi++) {
                int mb = wm * 32 + mi * 16;
                a[mi][0] = Ab[(mb + qid) * ASTR + kk];
                a[mi][1] = Ab[(mb + qid + 8) * ASTR + kk];
                a[mi][2] = Ab[(mb + qid) * ASTR + kk + 4];
                a[mi][3] = Ab[(mb + qid + 8) * ASTR + kk + 4];
            }
#pragma unroll
            for (int ni = 0; ni < 4; ni++) {
                int nb = (wn * 32 + ni * 8 + qid) * ASTR;
                uint32_t b10 = B1b[nb + kk], b11 = B1b[nb + kk + 4];
                uint32_t b30 = B3b[nb + kk], b31 = B3b[nb + kk + 4];
#pragma unroll
                for (int mi = 0; mi < 2; mi++) {
                    mma16(acc1[mi][ni], a[mi][0], a[mi][1], a[mi][2], a[mi][3], b10, b11);
                    mma16(acc3[mi][ni], a[mi][0], a[mi][1], a[mi][2], a[mi][3], b30, b31);
                }
            }
        }
        __syncthreads();
    }
#pragma unroll
    for (int mi = 0; mi < 2; mi++) {
        int rbase = row0 + wm * 32 + mi * 16 + qid;
#pragma unroll
        for (int half = 0; half < 2; half++) {
            int r = rbase + half * 8;
            __half* orow = g_hs + (size_t)r * IS + col0 + wn * 32;
#pragma unroll
            for (int ni = 0; ni < 4; ni++) {
                float v1a = acc1[mi][ni][half * 2], v1b = acc1[mi][ni][half * 2 + 1];
                float v3a = acc3[mi][ni][half * 2], v3b = acc3[mi][ni][half * 2 + 1];
                int c = ni * 8 + 2 * tig;
                orow[c]     = __float2half_rn(silu_f(v1a) * v3a);
                orow[c + 1] = __float2half_rn(silu_f(v1b) * v3b);
            }
        }
    }
}

// Routed down-projection + weighted scatter-add. BM=128, BN=128, warp tile 32x64.
__global__ __launch_bounds__(256) void k_down_routed_tc(
        const __half* __restrict__ w2, float* __restrict__ out) {
    const int e = blockIdx.z;
    const int ne = g_cnt[e];
    const int row0 = blockIdx.y * 128;
    if (row0 >= ne) return;
    const int col0 = blockIdx.x * 128;

    extern __shared__ uint32_t smem[];
    uint32_t* As = smem;                   // 2 * 128*ASTR
    uint32_t* Bs = smem + 2 * 128 * ASTR;  // 2 * 128*ASTR

    const int tid = threadIdx.x;
    const int lane = tid & 31, wid = tid >> 5;
    const int qid = lane >> 2, tig = lane & 3;
    const int wm = wid & 3, wn = wid >> 2;
    const int lr = tid >> 3;
    const int lch = (tid & 7) * 8;
    const int lcw = (tid & 7) * 4;

    const __half* ab = g_h + (size_t)e * T * IM;
    const __half* bb = w2 + (size_t)e * H * IM + (size_t)col0 * IM;

    float acc[2][8][4];
#pragma unroll
    for (int mi = 0; mi < 2; mi++)
#pragma unroll
        for (int ni = 0; ni < 8; ni++)
#pragma unroll
            for (int r = 0; r < 4; r++) acc[mi][ni][r] = 0.f;

    auto load_tile = [&](int buf, int k0) {
        uint32_t* Ab = As + buf * 128 * ASTR;
        uint32_t* Bb = Bs + buf * 128 * ASTR;
#pragma unroll
        for (int q = 0; q < 4; q++) {
            int r = lr + q * 32;
            cp16(sptr(&Ab[r * ASTR + lcw]), ab + (size_t)(row0 + r) * IM + k0 + lch,
                 (row0 + r < ne) ? 16 : 0);
            cp16(sptr(&Bb[r * ASTR + lcw]), bb + (size_t)r * IM + k0 + lch, 16);
        }
    };

    const int NK = IM / BKH;   // 16
    load_tile(0, 0);
    CP_COMMIT();
    for (int kt = 0; kt < NK; kt++) {
        int buf = kt & 1;
        if (kt + 1 < NK) load_tile(buf ^ 1, (kt + 1) * BKH);
        CP_COMMIT();
        CP_WAIT1();
        __syncthreads();
        uint32_t* Ab = As + buf * 128 * ASTR;
        uint32_t* Bb = Bs + buf * 128 * ASTR;
#pragma unroll
        for (int ks = 0; ks < 4; ks++) {
            const int kk = ks * 8 + tig;
            uint32_t a[2][4];
#pragma unroll
            for (int mi = 0; mi < 2; mi++) {
                int mb = wm * 32 + mi * 16;
                a[mi][0] = Ab[(mb + qid) * ASTR + kk];
                a[mi][1] = Ab[(mb + qid + 8) * ASTR + kk];
                a[mi][2] = Ab[(mb + qid) * ASTR + kk + 4];
                a[mi][3] = Ab[(mb + qid + 8) * ASTR + kk + 4];
            }
#pragma unroll
            for (int ni = 0; ni < 8; ni++) {
                int nb = (wn * 64 + ni * 8 + qid) * ASTR;
                uint32_t b0 = Bb[nb + kk], b1 = Bb[nb + kk + 4];
#pragma unroll
                for (int mi = 0; mi < 2; mi++)
                    mma16(acc[mi][ni], a[mi][0], a[mi][1], a[mi][2], a[mi][3], b0, b1);
            }
        }
        __syncthreads();
    }
#pragma unroll
    for (int mi = 0; mi < 2; mi++) {
        int rbase = row0 + wm * 32 + mi * 16 + qid;
#pragma unroll
        for (int half = 0; half < 2; half++) {
            int r = rbase + half * 8;
            if (r >= ne) continue;
            int t = g_tok[e * T + r];
            float wt = g_wt[e * T + r];
            float* orow = out + (size_t)t * H + col0 + wn * 64;
#pragma unroll
            for (int ni = 0; ni < 8; ni++) {
                int c = ni * 8 + 2 * tig;
                atomicAdd(&orow[c],     wt * acc[mi][ni][half * 2]);
                atomicAdd(&orow[c + 1], wt * acc[mi][ni][half * 2 + 1]);
            }
        }
    }
}

// Final: out += sgate * (hs @ sw2^T). BM=128, BN=128, warp tile 32x64.
__global__ __launch_bounds__(256) void k_final_tc(
        const __half* __restrict__ w2s, float* __restrict__ out) {
    const int row0 = blockIdx.y * 128;
    const int col0 = blockIdx.x * 128;

    extern __shared__ uint32_t smem[];
    uint32_t* As = smem;                   // 2 * 128*ASTR
    uint32_t* Bs = smem + 2 * 128 * ASTR;  // 2 * 128*ASTR

    const int tid = threadIdx.x;
    const int lane = tid & 31, wid = tid >> 5;
    const int qid = lane >> 2, tig = lane & 3;
    const int wm = wid & 3, wn = wid >> 2;
    const int lr = tid >> 3;
    const int lch = (tid & 7) * 8;
    const int lcw = (tid & 7) * 4;

    const __half* bb = w2s + (size_t)col0 * IS;

    float acc[2][8][4];
#pragma unroll
    for (int mi = 0; mi < 2; mi++)
#pragma unroll
        for (int ni = 0; ni < 8; ni++)
#pragma unroll
            for (int r = 0; r < 4; r++) acc[mi][ni][r] = 0.f;

    auto load_tile = [&](int buf, int k0) {
        uint32_t* Ab = As + buf * 128 * ASTR;
        uint32_t* Bb = Bs + buf * 128 * ASTR;
#pragma unroll
        for (int q = 0; q < 4; q++) {
            int r = lr + q * 32;
            cp16(sptr(&Ab[r * ASTR + lcw]), g_hs + (size_t)(row0 + r) * IS + k0 + lch, 16);
            cp16(sptr(&Bb[r * ASTR + lcw]), bb + (size_t)r * IS + k0 + lch, 16);
        }
    };

    const int NK = IS / BKH;   // 32
    load_tile(0, 0);
    CP_COMMIT();
    for (int kt = 0; kt < NK; kt++) {
        int buf = kt & 1;
        if (kt + 1 < NK) load_tile(buf ^ 1, (kt + 1) * BKH);
        CP_COMMIT();
        CP_WAIT1();
        __syncthreads();
        uint32_t* Ab = As + buf * 128 * ASTR;
        uint32_t* Bb = Bs + buf * 128 * ASTR;
#pragma unroll
        for (int ks = 0; ks < 4; ks++) {
            const int kk = ks * 8 + tig;
            uint32_t a[2][4];
#pragma unroll
            for (int mi = 0; mi < 2; mi++) {
                int mb = wm * 32 + mi * 16;
                a[mi][0] = Ab[(mb + qid) * ASTR + kk];
                a[mi][1] = Ab[(mb + qid + 8) * ASTR + kk];
                a[mi][2] = Ab[(mb + qid) * ASTR + kk + 4];
                a[mi][3] = Ab[(mb + qid + 8) * ASTR + kk + 4];
            }
#pragma unroll
            for (int ni = 0; ni < 8; ni++) {
                int nb = (wn * 64 + ni * 8 + qid) * ASTR;
                uint32_t b0 = Bb[nb + kk], b1 = Bb[nb + kk + 4];
#pragma unroll
                for (int mi = 0; mi < 2; mi++)
                    mma16(acc[mi][ni], a[mi][0], a[mi][1], a[mi][2], a[mi][3], b0, b1);
            }
        }
        __syncthreads();
    }
#pragma unroll
    for (int mi = 0; mi < 2; mi++) {
        int rbase = row0 + wm * 32 + mi * 16 + qid;
#pragma unroll
        for (int half = 0; half < 2; half++) {
            int r = rbase + half * 8;
            float sg = g_sgate[r];
            float* orow = out + (size_t)r * H + col0 + wn * 64;
#pragma unroll
            for (int ni = 0; ni < 8; ni++) {
                int c = ni * 8 + 2 * tig;
                orow[c]     += sg * acc[mi][ni][half * 2];
                orow[c + 1] += sg * acc[mi][ni][half * 2 + 1];
            }
        }
    }
}

// ---------------- launcher ----------------
extern "C" void kernel_launch(void* const* d_in, const int* in_sizes, int n_in,
                              void* d_out, int out_size) {
    const float* x   = (const float*)d_in[0];
    const float* gw  = (const float*)d_in[1];
    const float* w1  = (const float*)d_in[2];
    const float* w2  = (const float*)d_in[3];
    const float* w3  = (const float*)d_in[4];
    const float* sw1 = (const float*)d_in[5];
    const float* sw2 = (const float*)d_in[6];
    const float* sw3 = (const float*)d_in[7];
    const float* sgw = (const float*)d_in[8];

    float* out = (float*)d_out;
    float* logits = (out_size >= (int)((size_t)T * H + (size_t)T * E))
                        ? out + (size_t)T * H : nullptr;

    const int SM_UP   = 2 * (128 + 64 + 64) * ASTR * 4;  // 73728
    const int SM_GEMM = 2 * (128 + 128) * ASTR * 4;      // 73728

    cudaFuncSetAttribute(k_up_routed_tc,   cudaFuncAttributeMaxDynamicSharedMemorySize, SM_UP);
    cudaFuncSetAttribute(k_up_shared_tc,   cudaFuncAttributeMaxDynamicSharedMemorySize, SM_UP);
    cudaFuncSetAttribute(k_down_routed_tc, cudaFuncAttributeMaxDynamicSharedMemorySize, SM_GEMM);
    cudaFuncSetAttribute(k_final_tc,       cudaFuncAttributeMaxDynamicSharedMemorySize, SM_GEMM);

    void* p_xh;   cudaGetSymbolAddress(&p_xh,   g_xh);
    void* p_w1h;  cudaGetSymbolAddress(&p_w1h,  g_w1h);
    void* p_w3h;  cudaGetSymbolAddress(&p_w3h,  g_w3h);
    void* p_w2h;  cudaGetSymbolAddress(&p_w2h,  g_w2h);
    void* p_sw1h; cudaGetSymbolAddress(&p_sw1h, g_sw1h);
    void* p_sw3h; cudaGetSymbolAddress(&p_sw3h, g_sw3h);
    void* p_sw2h; cudaGetSymbolAddress(&p_sw2h, g_sw2h);

    k_zero_cnt<<<1, 32>>>();
    size_t nz = (size_t)T * H;
    if ((size_t)out_size < nz) nz = (size_t)out_size;
    cudaMemsetAsync(d_out, 0, nz * sizeof(float), 0);

    // fp32 -> fp16 conversion prologue (memory-bound)
    {
        const int TH = 256;
        int n8;
        n8 = T * H / 8;      k_to_half<<<(n8 + TH - 1) / TH, TH>>>(x,   (__half*)p_xh,   n8);
        n8 = E * IM * H / 8; k_to_half<<<(n8 + TH - 1) / TH, TH>>>(w1,  (__half*)p_w1h,  n8);
        n8 = E * IM * H / 8; k_to_half<<<(n8 + TH - 1) / TH, TH>>>(w3,  (__half*)p_w3h,  n8);
        n8 = E * H * IM / 8; k_to_half<<<(n8 + TH - 1) / TH, TH>>>(w2,  (__half*)p_w2h,  n8);
        n8 = IS * H / 8;     k_to_half<<<(n8 + TH - 1) / TH, TH>>>(sw1, (__half*)p_sw1h, n8);
        n8 = IS * H / 8;     k_to_half<<<(n8 + TH - 1) / TH, TH>>>(sw3, (__half*)p_sw3h, n8);
        n8 = H * IS / 8;     k_to_half<<<(n8 + TH - 1) / TH, TH>>>(sw2, (__half*)p_sw2h, n8);
    }

    k_router<<<T / 8, 256>>>(x, gw, sgw, logits);

    k_up_routed_tc  <<<dim3(IM / 64,  T / 128, E), 256, SM_UP>>>((const __half*)p_xh, (const __half*)p_w1h, (const __half*)p_w3h);
    k_down_routed_tc<<<dim3(H / 128,  T / 128, E), 256, SM_GEMM>>>((const __half*)p_w2h, out);

    k_up_shared_tc<<<dim3(IS / 64, T / 128), 256, SM_UP>>>((const __half*)p_xh, (const __half*)p_sw1h, (const __half*)p_sw3h);
    k_final_tc    <<<dim3(H / 128, T / 128), 256, SM_GEMM>>>((const __half*)p_sw2h, out);
}

// round 16
// speedup vs baseline: 1.0080x; 1.0080x over previous
#include <cuda_runtime.h>
#include <cuda_fp16.h>
#include <math.h>
#include <stdint.h>

#define T  8192
#define H  512
#define E  8
#define IM 1024
#define IS 2048

#define BKH  64   // K-chunk in halves (128 B per row)
#define ASTR 36   // words per row: 32 data + 4 pad = 144 B

// ---------------- device scratch (allocation-free) ----------------
__device__ int    g_cnt[E];
__device__ int    g_tok[E * T];
__device__ float  g_wt[E * T];
__device__ float  g_sgate[T];
__device__ __align__(16) __half g_h[(size_t)E * T * IM];
__device__ __align__(16) __half g_hs[(size_t)T * IS];
__device__ __align__(16) __half g_xh[(size_t)T * H];
__device__ __align__(16) __half g_w1h[(size_t)E * IM * H];
__device__ __align__(16) __half g_w3h[(size_t)E * IM * H];
__device__ __align__(16) __half g_w2h[(size_t)E * H * IM];
__device__ __align__(16) __half g_sw1h[(size_t)IS * H];
__device__ __align__(16) __half g_sw3h[(size_t)IS * H];
__device__ __align__(16) __half g_sw2h[(size_t)H * IS];

// ---------------- helpers ----------------
__device__ __forceinline__ void mma16(float* c,
        uint32_t a0, uint32_t a1, uint32_t a2, uint32_t a3,
        uint32_t b0, uint32_t b1) {
    asm volatile(
        "mma.sync.aligned.m16n8k16.row.col.f32.f16.f16.f32 "
        "{%0,%1,%2,%3}, {%4,%5,%6,%7}, {%8,%9}, {%0,%1,%2,%3};"
        : "+f"(c[0]), "+f"(c[1]), "+f"(c[2]), "+f"(c[3])
        : "r"(a0), "r"(a1), "r"(a2), "r"(a3), "r"(b0), "r"(b1));
}
__device__ __forceinline__ float silu_f(float v) { return v / (1.f + __expf(-v)); }
__device__ __forceinline__ uint32_t sptr(const void* p) {
    return (uint32_t)__cvta_generic_to_shared(p);
}
__device__ __forceinline__ void cp16(uint32_t dst, const void* src, int sz) {
    asm volatile("cp.async.cg.shared.global [%0], [%1], 16, %2;"
                 :: "r"(dst), "l"(src), "r"(sz));
}
#define CP_COMMIT() asm volatile("cp.async.commit_group;")
#define CP_WAIT1()  asm volatile("cp.async.wait_group 1;")

// ---------------- fused prologue: fp32 -> fp16 over all 7 tensors ----------------
struct CvtArgs {
    const float* src[7];
    __half*      dst[7];
    int          n8[7];
};

__global__ void k_to_half_all(CvtArgs a, int total8) {
    int i = blockIdx.x * blockDim.x + threadIdx.x;
    if (i >= total8) return;
    int s = 0, base = 0;
#pragma unroll
    for (int k = 0; k < 6; k++) {
        int adv = (i - base >= a.n8[s]) ? 1 : 0;
        base += adv ? a.n8[s] : 0;
        s += adv;
    }
    int j = i - base;
    const float4* s4 = (const float4*)a.src[s];
    float4 v0 = s4[2 * j], v1 = s4[2 * j + 1];
    __half2 h0 = __floats2half2_rn(v0.x, v0.y);
    __half2 h1 = __floats2half2_rn(v0.z, v0.w);
    __half2 h2 = __floats2half2_rn(v1.x, v1.y);
    __half2 h3 = __floats2half2_rn(v1.z, v1.w);
    uint4 o;
    o.x = *(uint32_t*)&h0; o.y = *(uint32_t*)&h1;
    o.z = *(uint32_t*)&h2; o.w = *(uint32_t*)&h3;
    ((uint4*)a.dst[s])[j] = o;
}

__global__ void k_zero_cnt() {
    if (threadIdx.x < E) g_cnt[threadIdx.x] = 0;
}

// One warp per token: router logits (fp32), softmax, top-2 dispatch, sigmoid gate.
__global__ void k_router(const float* __restrict__ x, const float* __restrict__ gw,
                         const float* __restrict__ sgw, float* __restrict__ logits_out) {
    const int warp = threadIdx.x >> 5;
    const int lane = threadIdx.x & 31;
    const int t = blockIdx.x * 8 + warp;
    if (t >= T) return;

    float xv[16];
    const float* xr = x + (size_t)t * H;
#pragma unroll
    for (int i = 0; i < 16; i++) xv[i] = xr[lane + 32 * i];

    float l[E];
#pragma unroll
    for (int e = 0; e < E; e++) {
        const float* w = gw + (size_t)e * H;
        float s = 0.f;
#pragma unroll
        for (int i = 0; i < 16; i++) s = fmaf(xv[i], w[lane + 32 * i], s);
#pragma unroll
        for (int off = 16; off > 0; off >>= 1) s += __shfl_xor_sync(0xffffffffu, s, off);
        l[e] = s;
    }
    float sd = 0.f;
#pragma unroll
    for (int i = 0; i < 16; i++) sd = fmaf(xv[i], sgw[lane + 32 * i], sd);
#pragma unroll
    for (int off = 16; off > 0; off >>= 1) sd += __shfl_xor_sync(0xffffffffu, sd, off);

    if (lane == 0) {
        if (logits_out) {
#pragma unroll
            for (int e = 0; e < E; e++) logits_out[(size_t)t * E + e] = l[e];
        }
        float m = l[0];
#pragma unroll
        for (int e = 1; e < E; e++) m = fmaxf(m, l[e]);
        float p[E], s = 0.f;
#pragma unroll
        for (int e = 0; e < E; e++) { p[e] = expf(l[e] - m); s += p[e]; }
        float inv = 1.f / s;
#pragma unroll
        for (int e = 0; e < E; e++) p[e] *= inv;
        int i1 = 0;
#pragma unroll
        for (int e = 1; e < E; e++) if (p[e] > p[i1]) i1 = e;
        int i2 = (i1 == 0) ? 1 : 0;
#pragma unroll
        for (int e = 0; e < E; e++) if (e != i1 && p[e] > p[i2]) i2 = e;

        int pos1 = atomicAdd(&g_cnt[i1], 1);
        g_tok[i1 * T + pos1] = t; g_wt[i1 * T + pos1] = p[i1];
        int pos2 = atomicAdd(&g_cnt[i2], 1);
        g_tok[i2 * T + pos2] = t; g_wt[i2 * T + pos2] = p[i2];

        g_sgate[t] = 1.f / (1.f + expf(-sd));
    }
}

// =====================================================================
// Unified FP16 GEMMs: routed experts (z < E) and shared expert (z == E)
// in ONE grid so the scheduler interleaves both chains (tail filling
// without streams). 55.3 KB smem (3 CTAs/SM), 2-stage cp.async pipeline.
// 256 threads = 8 warps, 4(m) x 2(n).
// =====================================================================

// Unified up-projection (dual GEMM): BM=128, BN=32, warp tile 32x16.
// z<E: h = silu(Xg@w1e^T)*(Xg@w3e^T); z==E: hs = silu(x@sw1^T)*(x@sw3^T)
__global__ __launch_bounds__(256) void k_up_all(
        const __half* __restrict__ xq,
        const __half* __restrict__ w1,  const __half* __restrict__ w3,
        const __half* __restrict__ sw1, const __half* __restrict__ sw3) {
    const int z = blockIdx.z;
    const bool shared = (z == E);
    const int ne = shared ? T : g_cnt[z];
    const int row0 = blockIdx.y * 128;
    if (row0 >= ne) return;
    const int col0 = blockIdx.x * 32;
    if (!shared && col0 >= IM) return;

    extern __shared__ uint32_t smem[];
    uint32_t* As  = smem;                       // 2 * 128*ASTR
    uint32_t* B1s = smem + 2 * 128 * ASTR;      // 2 * 32*ASTR
    uint32_t* B3s = B1s + 2 * 32 * ASTR;        // 2 * 32*ASTR

    const int tid = threadIdx.x;
    const int lane = tid & 31, wid = tid >> 5;
    const int qid = lane >> 2, tig = lane & 3;
    const int wm = wid & 3, wn = wid >> 2;
    const int lr = tid >> 3;
    const int lch = (tid & 7) * 8;
    const int lcw = (tid & 7) * 4;

    int atok[4];
#pragma unroll
    for (int q = 0; q < 4; q++) {
        int r = row0 + lr + q * 32;
        atok[q] = shared ? r : ((r < ne) ? g_tok[z * T + r] : -1);
    }
    const __half* w1b = shared ? (sw1 + (size_t)col0 * H)
                               : (w1 + (size_t)z * IM * H + (size_t)col0 * H);
    const __half* w3b = shared ? (sw3 + (size_t)col0 * H)
                               : (w3 + (size_t)z * IM * H + (size_t)col0 * H);

    float acc1[2][2][4], acc3[2][2][4];
#pragma unroll
    for (int mi = 0; mi < 2; mi++)
#pragma unroll
        for (int ni = 0; ni < 2; ni++)
#pragma unroll
            for (int r = 0; r < 4; r++) { acc1[mi][ni][r] = 0.f; acc3[mi][ni][r] = 0.f; }

    auto load_tile = [&](int buf, int k0) {
        uint32_t* Ab  = As  + buf * 128 * ASTR;
        uint32_t* B1b = B1s + buf * 32 * ASTR;
        uint32_t* B3b = B3s + buf * 32 * ASTR;
#pragma unroll
        for (int q = 0; q < 4; q++) {
            int r = lr + q * 32;
            const __half* src = (atok[q] >= 0) ? (xq + (size_t)atok[q] * H + k0 + lch) : xq;
            cp16(sptr(&Ab[r * ASTR + lcw]), src, (atok[q] >= 0) ? 16 : 0);
        }
        cp16(sptr(&B1b[lr * ASTR + lcw]), w1b + (size_t)lr * H + k0 + lch, 16);
        cp16(sptr(&B3b[lr * ASTR + lcw]), w3b + (size_t)lr * H + k0 + lch, 16);
    };

    const int NK = H / BKH;   // 8
    load_tile(0, 0);
    CP_COMMIT();
    for (int kt = 0; kt < NK; kt++) {
        int buf = kt & 1;
        if (kt + 1 < NK) load_tile(buf ^ 1, (kt + 1) * BKH);
        CP_COMMIT();
        CP_WAIT1();
        __syncthreads();
        uint32_t* Ab  = As  + buf * 128 * ASTR;
        uint32_t* B1b = B1s + buf * 32 * ASTR;
        uint32_t* B3b = B3s + buf * 32 * ASTR;
#pragma unroll
        for (int ks = 0; ks < 4; ks++) {
            const int kk = ks * 8 + tig;
            uint32_t a[2][4];
#pragma unroll
            for (int mi = 0; mi < 2; mi++) {
                int mb = wm * 32 + mi * 16;
                a[mi][0] = Ab[(mb + qid) * ASTR + kk];
                a[mi][1] = Ab[(mb + qid + 8) * ASTR + kk];
                a[mi][2] = Ab[(mb + qid) * ASTR + kk + 4];
                a[mi][3] = Ab[(mb + qid + 8) * ASTR + kk + 4];
            }
#pragma unroll
            for (int ni = 0; ni < 2; ni++) {
                int nb = (wn * 16 + ni * 8 + qid) * ASTR;
                uint32_t b10 = B1b[nb + kk], b11 = B1b[nb + kk + 4];
                uint32_t b30 = B3b[nb + kk], b31 = B3b[nb + kk + 4];
#pragma unroll
                for (int mi = 0; mi < 2; mi++) {
                    mma16(acc1[mi][ni], a[mi][0], a[mi][1], a[mi][2], a[mi][3], b10, b11);
                    mma16(acc3[mi][ni], a[mi][0], a[mi][1], a[mi][2], a[mi][3], b30, b31);
                }
            }
        }
        __syncthreads();
    }
#pragma unroll
    for (int mi = 0; mi < 2; mi++) {
        int rbase = row0 + wm * 32 + mi * 16 + qid;
#pragma unroll
        for (int half = 0; half < 2; half++) {
            int r = rbase + half * 8;
            if (r >= ne) continue;
            __half* orow = shared ? (g_hs + (size_t)r * IS + col0 + wn * 16)
                                  : (g_h + ((size_t)z * T + r) * IM + col0 + wn * 16);
#pragma unroll
            for (int ni = 0; ni < 2; ni++) {
                float v1a = acc1[mi][ni][half * 2], v1b = acc1[mi][ni][half * 2 + 1];
                float v3a = acc3[mi][ni][half * 2], v3b = acc3[mi][ni][half * 2 + 1];
                int c = ni * 8 + 2 * tig;
                orow[c]     = __float2half_rn(silu_f(v1a) * v3a);
                orow[c + 1] = __float2half_rn(silu_f(v1b) * v3b);
            }
        }
    }
}

// Unified down-projection (BM=128, BN=64, warp tile 32x32), atomicAdd into out.
// z<E: out += wt[t] * (h_e @ w2e^T); z==E: out += sgate * (hs @ sw2^T)
__global__ __launch_bounds__(256) void k_down_all(
        const __half* __restrict__ w2, const __half* __restrict__ sw2,
        float* __restrict__ out) {
    const int z = blockIdx.z;
    const bool shared = (z == E);
    const int ne = shared ? T : g_cnt[z];
    const int row0 = blockIdx.y * 128;
    if (row0 >= ne) return;
    const int col0 = blockIdx.x * 64;

    const int KS = shared ? IS : IM;            // runtime K-dim / row stride

    extern __shared__ uint32_t smem[];
    uint32_t* As = smem;                   // 2 * 128*ASTR
    uint32_t* Bs = smem + 2 * 128 * ASTR;  // 2 * 64*ASTR

    const int tid = threadIdx.x;
    const int lane = tid & 31, wid = tid >> 5;
    const int qid = lane >> 2, tig = lane & 3;
    const int wm = wid & 3, wn = wid >> 2;
    const int lr = tid >> 3;
    const int lch = (tid & 7) * 8;
    const int lcw = (tid & 7) * 4;

    const __half* ab = shared ? g_hs : (g_h + (size_t)z * T * IM);
    const __half* bb = shared ? (sw2 + (size_t)col0 * IS)
                              : (w2 + (size_t)z * H * IM + (size_t)col0 * IM);

    float acc[2][4][4];
#pragma unroll
    for (int mi = 0; mi < 2; mi++)
#pragma unroll
        for (int ni = 0; ni < 4; ni++)
#pragma unroll
            for (int r = 0; r < 4; r++) acc[mi][ni][r] = 0.f;

    auto load_tile = [&](int buf, int k0) {
        uint32_t* Ab = As + buf * 128 * ASTR;
        uint32_t* Bb = Bs + buf * 64 * ASTR;
#pragma unroll
        for (int q = 0; q < 4; q++) {
            int r = lr + q * 32;
            cp16(sptr(&Ab[r * ASTR + lcw]), ab + (size_t)(row0 + r) * KS + k0 + lch,
                 (row0 + r < ne) ? 16 : 0);
        }
#pragma unroll
        for (int q = 0; q < 2; q++) {
            int r = lr + q * 32;
            cp16(sptr(&Bb[r * ASTR + lcw]), bb + (size_t)r * KS + k0 + lch, 16);
        }
    };

    const int NK = KS / BKH;   // 16 or 32
    load_tile(0, 0);
    CP_COMMIT();
    for (int kt = 0; kt < NK; kt++) {
        int buf = kt & 1;
        if (kt + 1 < NK) load_tile(buf ^ 1, (kt + 1) * BKH);
        CP_COMMIT();
        CP_WAIT1();
        __syncthreads();
        uint32_t* Ab = As + buf * 128 * ASTR;
        uint32_t* Bb = Bs + buf * 64 * ASTR;
#pragma unroll
        for (int ks = 0; ks < 4; ks++) {
            const int kk = ks * 8 + tig;
            uint32_t a[2][4];
#pragma unroll
            for (int mi = 0; mi < 2; mi++) {
                int mb = wm * 32 + mi * 16;
                a[mi][0] = Ab[(mb + qid) * ASTR + kk];
                a[mi][1] = Ab[(mb + qid + 8) * ASTR + kk];
                a[mi][2] = Ab[(mb + qid) * ASTR + kk + 4];
                a[mi][3] = Ab[(mb + qid + 8) * ASTR + kk + 4];
            }
#pragma unroll
            for (int ni = 0; ni < 4; ni++) {
                int nb = (wn * 32 + ni * 8 + qid) * ASTR;
                uint32_t b0 = Bb[nb + kk], b1 = Bb[nb + kk + 4];
#pragma unroll
                for (int mi = 0; mi < 2; mi++)
                    mma16(acc[mi][ni], a[mi][0], a[mi][1], a[mi][2], a[mi][3], b0, b1);
            }
        }
        __syncthreads();
    }
#pragma unroll
    for (int mi = 0; mi < 2; mi++) {
        int rbase = row0 + wm * 32 + mi * 16 + qid;
#pragma unroll
        for (int half = 0; half < 2; half++) {
            int r = rbase + half * 8;
            if (r >= ne) continue;
            int t;
            float wt;
            if (shared) { t = r; wt = g_sgate[r]; }
            else        { t = g_tok[z * T + r]; wt = g_wt[z * T + r]; }
            float* orow = out + (size_t)t * H + col0 + wn * 32;
#pragma unroll
            for (int ni = 0; ni < 4; ni++) {
                int c = ni * 8 + 2 * tig;
                atomicAdd(&orow[c],     wt * acc[mi][ni][half * 2]);
                atomicAdd(&orow[c + 1], wt * acc[mi][ni][half * 2 + 1]);
            }
        }
    }
}

// ---------------- launcher ----------------
extern "C" void kernel_launch(void* const* d_in, const int* in_sizes, int n_in,
                              void* d_out, int out_size) {
    const float* x   = (const float*)d_in[0];
    const float* gw  = (const float*)d_in[1];
    const float* w1  = (const float*)d_in[2];
    const float* w2  = (const float*)d_in[3];
    const float* w3  = (const float*)d_in[4];
    const float* sw1 = (const float*)d_in[5];
    const float* sw2 = (const float*)d_in[6];
    const float* sw3 = (const float*)d_in[7];
    const float* sgw = (const float*)d_in[8];

    float* out = (float*)d_out;
    float* logits = (out_size >= (int)((size_t)T * H + (size_t)T * E))
                        ? out + (size_t)T * H : nullptr;

    const int SM_UP   = 2 * (128 + 32 + 32) * ASTR * 4;  // 55296
    const int SM_GEMM = 2 * (128 + 64) * ASTR * 4;       // 55296

    cudaFuncSetAttribute(k_up_all,   cudaFuncAttributeMaxDynamicSharedMemorySize, SM_UP);
    cudaFuncSetAttribute(k_down_all, cudaFuncAttributeMaxDynamicSharedMemorySize, SM_GEMM);

    void* p_xh;   cudaGetSymbolAddress(&p_xh,   g_xh);
    void* p_w1h;  cudaGetSymbolAddress(&p_w1h,  g_w1h);
    void* p_w3h;  cudaGetSymbolAddress(&p_w3h,  g_w3h);
    void* p_w2h;  cudaGetSymbolAddress(&p_w2h,  g_w2h);
    void* p_sw1h; cudaGetSymbolAddress(&p_sw1h, g_sw1h);
    void* p_sw3h; cudaGetSymbolAddress(&p_sw3h, g_sw3h);
    void* p_sw2h; cudaGetSymbolAddress(&p_sw2h, g_sw2h);

    k_zero_cnt<<<1, 32>>>();
    size_t nz = (size_t)T * H;
    if ((size_t)out_size < nz) nz = (size_t)out_size;
    cudaMemsetAsync(d_out, 0, nz * sizeof(float), 0);

    // fused fp32->fp16 conversion of all 7 operand tensors (1 launch)
    {
        CvtArgs a;
        a.src[0] = x;   a.dst[0] = (__half*)p_xh;   a.n8[0] = T * H / 8;
        a.src[1] = w1;  a.dst[1] = (__half*)p_w1h;  a.n8[1] = E * IM * H / 8;
        a.src[2] = w3;  a.dst[2] = (__half*)p_w3h;  a.n8[2] = E * IM * H / 8;
        a.src[3] = w2;  a.dst[3] = (__half*)p_w2h;  a.n8[3] = E * H * IM / 8;
        a.src[4] = sw1; a.dst[4] = (__half*)p_sw1h; a.n8[4] = IS * H / 8;
        a.src[5] = sw3; a.dst[5] = (__half*)p_sw3h; a.n8[5] = IS * H / 8;
        a.src[6] = sw2; a.dst[6] = (__half*)p_sw2h; a.n8[6] = H * IS / 8;
        int total8 = 0;
        for (int i = 0; i < 7; i++) total8 += a.n8[i];
        k_to_half_all<<<(total8 + 255) / 256, 256>>>(a, total8);
    }

    k_router<<<T / 8, 256>>>(x, gw, sgw, logits);

    // unified up: routed experts z=0..E-1 (cols 0..IM), shared z=E (cols 0..IS)
    k_up_all<<<dim3(IS / 32, T / 128, E + 1), 256, SM_UP>>>(
        (const __half*)p_xh,
        (const __half*)p_w1h, (const __half*)p_w3h,
        (const __half*)p_sw1h, (const __half*)p_sw3h);

    // unified down: routed scatter z=0..E-1, shared final z=E
    k_down_all<<<dim3(H / 64, T / 128, E + 1), 256, SM_GEMM>>>(
        (const __half*)p_w2h, (const __half*)p_sw2h, out);
}